// round 10
// baseline (speedup 1.0000x reference)
#include <cuda_runtime.h>

typedef unsigned long long u64;
typedef unsigned int u32;
typedef unsigned short u16;

#define HW (512*512)          // 262144 = 2^18 pixels per batch
#define NPIX (2*HW)           // 524288
#define NBUCK 256             // 16x16 octahedral buckets
#define NREG (2*NBUCK)        // (batch,bucket) regions
#define NSLOT (NPIX + NREG*32)   // 540672 padded slots
#define HGRID (NSLOT/256)     // 2112 blocks covers all slots

// ---------------- device scratch ----------------
// Shade table: per batch b (2), per m-pair mp (240; eh>=1 lights), 16 floats (64B):
//   [hx0,hx1, hy0,hy1, hz0,hz1, wr0,wr1, wg0,wg1, wb0,wb1, pad x4]
__device__ __align__(16) float g_table[2 * 240 * 16];
__device__ u32 g_maxbits;
__device__ u32 g_hist[NREG];
__device__ u32 g_offset[NREG];
__device__ u32 g_cursor[NREG];
__device__ u32 g_order[NSLOT];
__device__ u16 g_obk[NSLOT];          // region id per slot (batch*256+bucket)
__device__ u16 g_list[NBUCK * 240];   // per-bucket light-pair list
__device__ u32 g_listlen[NBUCK];

// ---------------- packed f32x2 helpers ----------------
__device__ __forceinline__ u64 pk2(float lo, float hi) {
    u64 r;
    asm("mov.b64 %0, {%1, %2};" : "=l"(r) : "r"(__float_as_uint(lo)), "r"(__float_as_uint(hi)));
    return r;
}
__device__ __forceinline__ void unpk2(u64 v, float& lo, float& hi) {
    u32 a, b;
    asm("mov.b64 {%0, %1}, %2;" : "=r"(a), "=r"(b) : "l"(v));
    lo = __uint_as_float(a); hi = __uint_as_float(b);
}
__device__ __forceinline__ u64 dup2(float x) { return pk2(x, x); }
__device__ __forceinline__ u64 fma2_(u64 a, u64 b, u64 c) {
    u64 d; asm("fma.rn.f32x2 %0, %1, %2, %3;" : "=l"(d) : "l"(a), "l"(b), "l"(c)); return d;
}
__device__ __forceinline__ u64 mul2_(u64 a, u64 b) {
    u64 d; asm("mul.rn.f32x2 %0, %1, %2;" : "=l"(d) : "l"(a), "l"(b)); return d;
}
__device__ __forceinline__ u64 relu2(u64 s) {
    u32 lo, hi;
    asm("mov.b64 {%0,%1}, %2;" : "=r"(lo), "=r"(hi) : "l"(s));
    asm("max.s32 %0, %0, 0;" : "+r"(lo));
    asm("max.s32 %0, %0, 0;" : "+r"(hi));
    u64 r;
    asm("mov.b64 %0, {%1,%2};" : "=l"(r) : "r"(lo), "r"(hi));
    return r;
}
__device__ __forceinline__ u64 max2_s32(u64 m, u64 s) {
    u32 ml, mh, sl, sh;
    asm("mov.b64 {%0,%1}, %2;" : "=r"(ml), "=r"(mh) : "l"(m));
    asm("mov.b64 {%0,%1}, %2;" : "=r"(sl), "=r"(sh) : "l"(s));
    asm("max.s32 %0, %0, %1;" : "+r"(ml) : "r"(sl));
    asm("max.s32 %0, %0, %1;" : "+r"(mh) : "r"(sh));
    u64 r;
    asm("mov.b64 %0, {%1,%2};" : "=l"(r) : "r"(ml), "r"(mh));
    return r;
}

// ---------------- octahedral bucket mapping ----------------
__device__ __forceinline__ int oct_bucket(float nx, float ny, float nz) {
    float a = fabsf(nx) + fabsf(ny) + fabsf(nz);
    float inva = 1.0f / fmaxf(a, 1e-20f);
    float u = nx * inva, v = ny * inva;
    if (nz < 0.0f) {
        float uu = copysignf(1.0f - fabsf(v), u);
        float vv = copysignf(1.0f - fabsf(u), v);
        u = uu; v = vv;
    }
    int bu = min(15, max(0, (int)((u * 0.5f + 0.5f) * 16.0f)));
    int bv = min(15, max(0, (int)((v * 0.5f + 0.5f) * 16.0f)));
    return bv * 16 + bu;
}
__device__ __forceinline__ void oct_decode(float u, float v, float& x, float& y, float& z) {
    float zz = 1.0f - fabsf(u) - fabsf(v);
    float uu = u, vv = v;
    if (zz < 0.0f) {
        uu = copysignf(1.0f - fabsf(v), u);
        vv = copysignf(1.0f - fabsf(u), v);
    }
    float inv = rsqrtf(uu * uu + vv * vv + zz * zz);
    x = uu * inv; y = vv * inv; z = zz * inv;
}

// ---------------- per-pixel normal prep ----------------
__device__ __forceinline__ void load_normal(const float* __restrict__ nptr,
                                            float& nx, float& ny, float& nz) {
    float c0 = nptr[0], c1 = nptr[1], c2 = nptr[2];
    nx = (c2 - 0.5f) * 2.0f;
    ny = (c1 - 0.5f) * 2.0f;
    nz = (c0 - 0.5f) * 2.0f;
    float nn = sqrtf(nx * nx + ny * ny + nz * nz);
    float iv = 1.0f / fmaxf(nn, 1e-12f);
    nx *= iv; ny *= iv; nz *= iv;
}

// ---------------- kernel 0: tables + counter reset ----------------
__global__ void k_setup(const float* __restrict__ env) {
    int m = threadIdx.x;              // 0..511
    if (m == 0) g_maxbits = 0u;
    if (m < NREG) { g_hist[m] = 0u; g_cursor[m] = 0u; }

    int eh = m >> 5, ew = m & 31;
    const float PI_F = 3.14159274101257324e+00f;
    float phi = ((float)eh * (1.0f / 16.0f)) * PI_F;
    float th  = (((float)ew * (1.0f / 32.0f)) * 2.0f) * PI_F;

    float sp = sinf(phi), cp = cosf(phi);
    float st = sinf(th),  ct = cosf(th);

    float hx = st * sp;
    float hy = cp;
    float hz = 1.0f - ct * sp;
    float nrm = sqrtf(hx * hx + hy * hy + hz * hz);
    float rin = 1.0f / nrm;
    hx *= rin; hy *= rin; hz *= rin;

    if (m >= 32) {                    // eh>=1: 480 lights -> 240 pairs
        int i = m - 32, mp = i >> 1, half = i & 1;
        const float SC = (float)(1.0 / 60.0);
        float sw = sp * SC;
        #pragma unroll
        for (int b = 0; b < 2; ++b) {
            float* row = g_table + (b * 240 + mp) * 16;
            row[0 + half]  = hx;
            row[2 + half]  = hy;
            row[4 + half]  = hz;
            const float* e = env + (b * 512 + m) * 3;
            row[6 + half]  = e[0] * sw;
            row[8 + half]  = e[1] * sw;
            row[10 + half] = e[2] * sw;
            if (half == 0) { row[12] = 0.f; row[13] = 0.f; row[14] = 0.f; row[15] = 0.f; }
        }
    }
}

// ---------------- kernel 1: global max (R8, unchanged) ----------------
__global__ void __launch_bounds__(256, 2) k_max(const float* __restrict__ normal) {
    __shared__ float4 tab[960];
    __shared__ float wm[8];
    const float4* gt = (const float4*)g_table;
    for (int i = threadIdx.x; i < 960; i += 256) tab[i] = gt[i];
    __syncthreads();

    int p0 = blockIdx.x * 256 + threadIdx.x;
    int p1 = p0 + 262144;
    float ax, ay, az, bx, by, bz;
    load_normal(normal + p0 * 3, ax, ay, az);
    load_normal(normal + p1 * 3, bx, by, bz);
    u64 ax2 = dup2(ax), ay2 = dup2(ay), az2 = dup2(az);
    u64 bx2 = dup2(bx), by2 = dup2(by), bz2 = dup2(bz);

    const float R2I = 0.70710678118654752f;
    float mx = fmaxf(fmaxf((ay + az) * R2I, (by + bz) * R2I), 0.0f);

    u64 ma = 0ull, mb = 0ull;
    #pragma unroll 8
    for (int mp = 0; mp < 240; ++mp) {
        float4 q0 = tab[mp * 4 + 0];
        float4 q1 = tab[mp * 4 + 1];
        u64 hx01 = pk2(q0.x, q0.y), hy01 = pk2(q0.z, q0.w), hz01 = pk2(q1.x, q1.y);
        u64 sa = fma2_(ax2, hx01, fma2_(ay2, hy01, mul2_(az2, hz01)));
        u64 sb = fma2_(bx2, hx01, fma2_(by2, hy01, mul2_(bz2, hz01)));
        ma = max2_s32(ma, sa);
        mb = max2_s32(mb, sb);
    }
    float l0, h0, l1, h1;
    unpk2(ma, l0, h0); unpk2(mb, l1, h1);
    mx = fmaxf(mx, fmaxf(fmaxf(l0, h0), fmaxf(l1, h1)));

    #pragma unroll
    for (int o = 16; o; o >>= 1) mx = fmaxf(mx, __shfl_xor_sync(0xffffffffu, mx, o));
    if ((threadIdx.x & 31) == 0) wm[threadIdx.x >> 5] = mx;
    __syncthreads();
    if (threadIdx.x == 0) {
        float m2 = wm[0];
        #pragma unroll
        for (int i = 1; i < 8; ++i) m2 = fmaxf(m2, wm[i]);
        atomicMax(&g_maxbits, __float_as_uint(m2));
    }
}

// ---------------- kernel 2: per-bucket light lists (needs gm) ----------------
__global__ void k_lists() {
    int k = threadIdx.x;              // 0..255 = bucket
    int bu = k & 15, bv = k >> 4;
    float uc = ((float)bu + 0.5f) * (1.0f / 16.0f) * 2.0f - 1.0f;
    float vc = ((float)bv + 0.5f) * (1.0f / 16.0f) * 2.0f - 1.0f;
    float cx, cy, cz;
    oct_decode(uc, vc, cx, cy, cz);

    // bucket angular radius bound from 4 cell corners
    float mind = 1.0f;
    #pragma unroll
    for (int c = 0; c < 4; ++c) {
        float ucr = ((float)(bu + (c & 1))) * (1.0f / 16.0f) * 2.0f - 1.0f;
        float vcr = ((float)(bv + (c >> 1))) * (1.0f / 16.0f) * 2.0f - 1.0f;
        float x, y, z;
        oct_decode(ucr, vcr, x, y, z);
        mind = fminf(mind, cx * x + cy * y + cz * z);
    }
    float gm = __uint_as_float(g_maxbits);
    float dth = fminf(0.70f * gm, 0.999f);
    float theta = acosf(dth) + acosf(fminf(fmaxf(mind, -1.0f), 1.0f)) + 0.09f;
    float cth = (theta >= 3.1f) ? -1.1f : cosf(theta);

    int cnt = 0;
    for (int mp = 0; mp < 240; ++mp) {
        const float* row = g_table + mp * 16;   // batch 0 (h batch-independent)
        float d0 = cx * row[0] + cy * row[2] + cz * row[4];
        float d1 = cx * row[1] + cy * row[3] + cz * row[5];
        if (fmaxf(d0, d1) > cth) g_list[k * 240 + cnt++] = (u16)mp;
    }
    g_listlen[k] = (u32)cnt;
}

// ---------------- kernel 3: histogram + poison ----------------
__global__ void k_hist(const float* __restrict__ normal) {
    __shared__ u32 sh[NREG];
    for (int i = threadIdx.x; i < NREG; i += 256) sh[i] = 0u;
    __syncthreads();

    int p = blockIdx.x * 256 + threadIdx.x;     // < NSLOT
    g_order[p] = 0xFFFFFFFFu;                   // poison every slot, every launch
    if (p < NPIX) {
        float nx, ny, nz;
        load_normal(normal + p * 3, nx, ny, nz);
        int r = (p >> 18) * NBUCK + oct_bucket(nx, ny, nz);
        atomicAdd(&sh[r], 1u);
    }
    __syncthreads();
    for (int i = threadIdx.x; i < NREG; i += 256)
        if (sh[i]) atomicAdd(&g_hist[i], sh[i]);
}

// ---------------- kernel 4: exclusive scan of padded counts ----------------
__global__ void k_scan() {
    __shared__ u32 s[NREG];
    int i = threadIdx.x;               // 512 threads
    u32 padded = (g_hist[i] + 31u) & ~31u;
    s[i] = padded;
    __syncthreads();
    for (int off = 1; off < NREG; off <<= 1) {
        u32 t = 0;
        if (i >= off) t = s[i - off];
        __syncthreads();
        if (i >= off) s[i] += t;
        __syncthreads();
    }
    g_offset[i] = s[i] - padded;       // exclusive, warp-aligned
}

// ---------------- kernel 5: scatter pixel indices ----------------
__global__ void k_scatter(const float* __restrict__ normal) {
    int p = blockIdx.x * 256 + threadIdx.x;     // < NPIX (grid 2048)
    float nx, ny, nz;
    load_normal(normal + p * 3, nx, ny, nz);
    int r = (p >> 18) * NBUCK + oct_bucket(nx, ny, nz);
    u32 slot = g_offset[r] + atomicAdd(&g_cursor[r], 1u);
    g_order[slot] = (u32)p;
    g_obk[slot] = (u16)r;
}

// ---------------- kernel 6: binned shade ----------------
__global__ void __launch_bounds__(256, 2) k_shade(const float* __restrict__ normal,
                                                  float* __restrict__ out) {
    __shared__ float4 tab[2 * 960];    // both batch tables, 30KB
    for (int i = threadIdx.x; i < 2 * 960; i += 256)
        tab[i] = ((const float4*)g_table)[i];
    __syncthreads();

    int slot = blockIdx.x * 256 + threadIdx.x;  // < NSLOT
    u32 pix = g_order[slot];
    bool valid = (pix != 0xFFFFFFFFu);
    u32 msk = __ballot_sync(0xffffffffu, valid);
    if (msk == 0u) return;
    int src = __ffs(msk) - 1;
    u32 r = valid ? (u32)g_obk[slot] : 0u;
    r = __shfl_sync(0xffffffffu, r, src);
    int bucket = (int)(r & 255u);
    int batch  = (int)(r >> 8);

    int p = valid ? (int)pix : 0;
    float nx, ny, nz;
    load_normal(normal + p * 3, nx, ny, nz);

    float gm = __uint_as_float(g_maxbits);
    float sc = 1.0f / gm;
    u64 nx2 = dup2(nx * sc), ny2 = dup2(ny * sc), nz2 = dup2(nz * sc);

    int len = (int)g_listlen[bucket];
    const u16* L = g_list + bucket * 240;
    const float4* T = &tab[batch * 960];

    u64 Ar = 0ull, Ag = 0ull, Ab = 0ull;
    #pragma unroll 4
    for (int j = 0; j < len; ++j) {
        int mp = (int)L[j];
        float4 q0 = T[mp * 4 + 0];
        float4 q1 = T[mp * 4 + 1];
        float4 q2 = T[mp * 4 + 2];
        u64 hx01 = pk2(q0.x, q0.y), hy01 = pk2(q0.z, q0.w), hz01 = pk2(q1.x, q1.y);
        u64 wr01 = pk2(q1.z, q1.w), wg01 = pk2(q2.x, q2.y), wb01 = pk2(q2.z, q2.w);

        u64 s = fma2_(nx2, hx01, fma2_(ny2, hy01, mul2_(nz2, hz01)));
        u64 c = relu2(s);
        c = mul2_(c, c);                 // ^2
        c = mul2_(c, c);                 // ^4
        c = mul2_(c, c);                 // ^8
        c = mul2_(c, c);                 // ^16
        c = mul2_(c, c);                 // ^32
        c = mul2_(c, c);                 // ^64
        Ar = fma2_(c, wr01, Ar);
        Ag = fma2_(c, wg01, Ag);
        Ab = fma2_(c, wb01, Ab);
    }

    if (valid) {
        float r0, r1, g0, g1, b0, b1;
        unpk2(Ar, r0, r1); unpk2(Ag, g0, g1); unpk2(Ab, b0, b1);
        int i = p & (HW - 1);
        int ob = batch * 3 * HW + i;
        out[ob]          = r0 + r1;
        out[ob + HW]     = g0 + g1;
        out[ob + 2 * HW] = b0 + b1;
    }
}

// ---------------- launch ----------------
extern "C" void kernel_launch(void* const* d_in, const int* in_sizes, int n_in,
                              void* d_out, int out_size) {
    const float* env    = (const float*)d_in[0];
    const float* normal = (const float*)d_in[1];
    if (n_in >= 2 && in_sizes[0] > in_sizes[1]) {
        env    = (const float*)d_in[1];
        normal = (const float*)d_in[0];
    }
    k_setup<<<1, 512>>>(env);
    k_max<<<1024, 256>>>(normal);
    k_lists<<<1, 256>>>();
    k_hist<<<HGRID, 256>>>(normal);
    k_scan<<<1, NREG>>>();
    k_scatter<<<2048, 256>>>(normal);
    k_shade<<<HGRID, 256>>>(normal, (float*)d_out);
}

// round 11
// speedup vs baseline: 1.0376x; 1.0376x over previous
#include <cuda_runtime.h>

typedef unsigned long long u64;
typedef unsigned int u32;
typedef unsigned short u16;

#define HW (512*512)            // 262144 pixels per batch
#define NPIX (2*HW)             // 524288
#define NBUCK 256               // 16x16 octahedral buckets
#define NREG (2*NBUCK)          // (batch,bucket) regions = 512
#define NSLOT (NPIX + NREG*64)  // 557056 slots (regions padded to 64)
#define NGRP (NSLOT/64)         // 8704 warp-groups
#define SGRID (NSLOT/512)       // 1088 shade blocks (8 warps x 64 slots)

// ---------------- device scratch ----------------
__device__ __align__(16) float g_table[2 * 240 * 16];
__device__ u32 g_maxbits;
__device__ u32 g_hist[NREG];
__device__ u32 g_offset[NREG];
__device__ u32 g_cursor[NREG];
__device__ u32 g_order[NSLOT];
__device__ u16 g_pixreg[NPIX];        // region per pixel (from k_hist)
__device__ u16 g_grpreg[NGRP];        // region per 64-slot group (from k_scan)
__device__ u16 g_list[NBUCK * 240];   // per-bucket light-pair list
__device__ u32 g_listlen[NBUCK];

// ---------------- packed f32x2 helpers ----------------
__device__ __forceinline__ u64 pk2(float lo, float hi) {
    u64 r;
    asm("mov.b64 %0, {%1, %2};" : "=l"(r) : "r"(__float_as_uint(lo)), "r"(__float_as_uint(hi)));
    return r;
}
__device__ __forceinline__ void unpk2(u64 v, float& lo, float& hi) {
    u32 a, b;
    asm("mov.b64 {%0, %1}, %2;" : "=r"(a), "=r"(b) : "l"(v));
    lo = __uint_as_float(a); hi = __uint_as_float(b);
}
__device__ __forceinline__ u64 dup2(float x) { return pk2(x, x); }
__device__ __forceinline__ u64 fma2_(u64 a, u64 b, u64 c) {
    u64 d; asm("fma.rn.f32x2 %0, %1, %2, %3;" : "=l"(d) : "l"(a), "l"(b), "l"(c)); return d;
}
__device__ __forceinline__ u64 mul2_(u64 a, u64 b) {
    u64 d; asm("mul.rn.f32x2 %0, %1, %2;" : "=l"(d) : "l"(a), "l"(b)); return d;
}
__device__ __forceinline__ u64 relu2(u64 s) {
    u32 lo, hi;
    asm("mov.b64 {%0,%1}, %2;" : "=r"(lo), "=r"(hi) : "l"(s));
    asm("max.s32 %0, %0, 0;" : "+r"(lo));
    asm("max.s32 %0, %0, 0;" : "+r"(hi));
    u64 r;
    asm("mov.b64 %0, {%1,%2};" : "=l"(r) : "r"(lo), "r"(hi));
    return r;
}
__device__ __forceinline__ u64 max2_s32(u64 m, u64 s) {
    u32 ml, mh, sl, sh;
    asm("mov.b64 {%0,%1}, %2;" : "=r"(ml), "=r"(mh) : "l"(m));
    asm("mov.b64 {%0,%1}, %2;" : "=r"(sl), "=r"(sh) : "l"(s));
    asm("max.s32 %0, %0, %1;" : "+r"(ml) : "r"(sl));
    asm("max.s32 %0, %0, %1;" : "+r"(mh) : "r"(sh));
    u64 r;
    asm("mov.b64 %0, {%1,%2};" : "=l"(r) : "r"(ml), "r"(mh));
    return r;
}

// ---------------- octahedral bucket mapping ----------------
__device__ __forceinline__ int oct_bucket(float nx, float ny, float nz) {
    float a = fabsf(nx) + fabsf(ny) + fabsf(nz);
    float inva = 1.0f / fmaxf(a, 1e-20f);
    float u = nx * inva, v = ny * inva;
    if (nz < 0.0f) {
        float uu = copysignf(1.0f - fabsf(v), u);
        float vv = copysignf(1.0f - fabsf(u), v);
        u = uu; v = vv;
    }
    int bu = min(15, max(0, (int)((u * 0.5f + 0.5f) * 16.0f)));
    int bv = min(15, max(0, (int)((v * 0.5f + 0.5f) * 16.0f)));
    return bv * 16 + bu;
}
__device__ __forceinline__ void oct_decode(float u, float v, float& x, float& y, float& z) {
    float zz = 1.0f - fabsf(u) - fabsf(v);
    float uu = u, vv = v;
    if (zz < 0.0f) {
        uu = copysignf(1.0f - fabsf(v), u);
        vv = copysignf(1.0f - fabsf(u), v);
    }
    float inv = rsqrtf(uu * uu + vv * vv + zz * zz);
    x = uu * inv; y = vv * inv; z = zz * inv;
}

// ---------------- per-pixel normal prep ----------------
__device__ __forceinline__ void load_normal(const float* __restrict__ nptr,
                                            float& nx, float& ny, float& nz) {
    float c0 = nptr[0], c1 = nptr[1], c2 = nptr[2];
    nx = (c2 - 0.5f) * 2.0f;
    ny = (c1 - 0.5f) * 2.0f;
    nz = (c0 - 0.5f) * 2.0f;
    float nn = sqrtf(nx * nx + ny * ny + nz * nz);
    float iv = 1.0f / fmaxf(nn, 1e-12f);
    nx *= iv; ny *= iv; nz *= iv;
}

// ---------------- kernel 0: tables + counter reset ----------------
__global__ void k_setup(const float* __restrict__ env) {
    int m = threadIdx.x;              // 0..511
    if (m == 0) g_maxbits = 0u;
    g_hist[m] = 0u; g_cursor[m] = 0u;

    int eh = m >> 5, ew = m & 31;
    const float PI_F = 3.14159274101257324e+00f;
    float phi = ((float)eh * (1.0f / 16.0f)) * PI_F;
    float th  = (((float)ew * (1.0f / 32.0f)) * 2.0f) * PI_F;

    float sp = sinf(phi), cp = cosf(phi);
    float st = sinf(th),  ct = cosf(th);

    float hx = st * sp;
    float hy = cp;
    float hz = 1.0f - ct * sp;
    float nrm = sqrtf(hx * hx + hy * hy + hz * hz);
    float rin = 1.0f / nrm;
    hx *= rin; hy *= rin; hz *= rin;

    if (m >= 32) {                    // eh>=1: 480 lights -> 240 pairs
        int i = m - 32, mp = i >> 1, half = i & 1;
        const float SC = (float)(1.0 / 60.0);
        float sw = sp * SC;
        #pragma unroll
        for (int b = 0; b < 2; ++b) {
            float* row = g_table + (b * 240 + mp) * 16;
            row[0 + half]  = hx;
            row[2 + half]  = hy;
            row[4 + half]  = hz;
            const float* e = env + (b * 512 + m) * 3;
            row[6 + half]  = e[0] * sw;
            row[8 + half]  = e[1] * sw;
            row[10 + half] = e[2] * sw;
            if (half == 0) { row[12] = 0.f; row[13] = 0.f; row[14] = 0.f; row[15] = 0.f; }
        }
    }
}

// ---------------- kernel 1: global max (R8, unchanged) ----------------
__global__ void __launch_bounds__(256, 2) k_max(const float* __restrict__ normal) {
    __shared__ float4 tab[960];
    __shared__ float wm[8];
    const float4* gt = (const float4*)g_table;
    for (int i = threadIdx.x; i < 960; i += 256) tab[i] = gt[i];
    __syncthreads();

    int p0 = blockIdx.x * 256 + threadIdx.x;
    int p1 = p0 + 262144;
    float ax, ay, az, bx, by, bz;
    load_normal(normal + p0 * 3, ax, ay, az);
    load_normal(normal + p1 * 3, bx, by, bz);
    u64 ax2 = dup2(ax), ay2 = dup2(ay), az2 = dup2(az);
    u64 bx2 = dup2(bx), by2 = dup2(by), bz2 = dup2(bz);

    const float R2I = 0.70710678118654752f;
    float mx = fmaxf(fmaxf((ay + az) * R2I, (by + bz) * R2I), 0.0f);

    u64 ma = 0ull, mb = 0ull;
    #pragma unroll 8
    for (int mp = 0; mp < 240; ++mp) {
        float4 q0 = tab[mp * 4 + 0];
        float4 q1 = tab[mp * 4 + 1];
        u64 hx01 = pk2(q0.x, q0.y), hy01 = pk2(q0.z, q0.w), hz01 = pk2(q1.x, q1.y);
        u64 sa = fma2_(ax2, hx01, fma2_(ay2, hy01, mul2_(az2, hz01)));
        u64 sb = fma2_(bx2, hx01, fma2_(by2, hy01, mul2_(bz2, hz01)));
        ma = max2_s32(ma, sa);
        mb = max2_s32(mb, sb);
    }
    float l0, h0, l1, h1;
    unpk2(ma, l0, h0); unpk2(mb, l1, h1);
    mx = fmaxf(mx, fmaxf(fmaxf(l0, h0), fmaxf(l1, h1)));

    #pragma unroll
    for (int o = 16; o; o >>= 1) mx = fmaxf(mx, __shfl_xor_sync(0xffffffffu, mx, o));
    if ((threadIdx.x & 31) == 0) wm[threadIdx.x >> 5] = mx;
    __syncthreads();
    if (threadIdx.x == 0) {
        float m2 = wm[0];
        #pragma unroll
        for (int i = 1; i < 8; ++i) m2 = fmaxf(m2, wm[i]);
        atomicMax(&g_maxbits, __float_as_uint(m2));
    }
}

// ---------------- kernel 2: per-bucket light lists ----------------
__global__ void k_lists() {
    int k = threadIdx.x;              // bucket
    int bu = k & 15, bv = k >> 4;
    float uc = ((float)bu + 0.5f) * (1.0f / 16.0f) * 2.0f - 1.0f;
    float vc = ((float)bv + 0.5f) * (1.0f / 16.0f) * 2.0f - 1.0f;
    float cx, cy, cz;
    oct_decode(uc, vc, cx, cy, cz);

    float mind = 1.0f;
    #pragma unroll
    for (int c = 0; c < 4; ++c) {
        float ucr = ((float)(bu + (c & 1))) * (1.0f / 16.0f) * 2.0f - 1.0f;
        float vcr = ((float)(bv + (c >> 1))) * (1.0f / 16.0f) * 2.0f - 1.0f;
        float x, y, z;
        oct_decode(ucr, vcr, x, y, z);
        mind = fminf(mind, cx * x + cy * y + cz * z);
    }
    float gm = __uint_as_float(g_maxbits);
    float dth = fminf(0.70f * gm, 0.999f);
    float theta = acosf(dth) + acosf(fminf(fmaxf(mind, -1.0f), 1.0f)) + 0.09f;
    float cth = (theta >= 3.1f) ? -1.1f : cosf(theta);

    int cnt = 0;
    for (int mp = 0; mp < 240; ++mp) {
        const float* row = g_table + mp * 16;
        float d0 = cx * row[0] + cy * row[2] + cz * row[4];
        float d1 = cx * row[1] + cy * row[3] + cz * row[5];
        if (fmaxf(d0, d1) > cth) g_list[k * 240 + cnt++] = (u16)mp;
    }
    g_listlen[k] = (u32)cnt;
}

// ---------------- kernel 3: histogram + region cache ----------------
__global__ void k_hist(const float* __restrict__ normal) {
    __shared__ u32 sh[NREG];
    for (int i = threadIdx.x; i < NREG; i += 256) sh[i] = 0u;
    __syncthreads();

    int p = blockIdx.x * 256 + threadIdx.x;     // grid 2048 -> p < NPIX
    float nx, ny, nz;
    load_normal(normal + p * 3, nx, ny, nz);
    int r = (p >> 18) * NBUCK + oct_bucket(nx, ny, nz);
    g_pixreg[p] = (u16)r;
    atomicAdd(&sh[r], 1u);
    __syncthreads();
    for (int i = threadIdx.x; i < NREG; i += 256)
        if (sh[i]) atomicAdd(&g_hist[i], sh[i]);
}

// ---------------- kernel 4: scan (pad 64) + group->region map ----------------
__global__ void k_scan() {
    __shared__ u32 s[NREG];
    int i = threadIdx.x;               // 512 threads
    u32 padded = (g_hist[i] + 63u) & ~63u;
    s[i] = padded;
    __syncthreads();
    for (int off = 1; off < NREG; off <<= 1) {
        u32 t = 0;
        if (i >= off) t = s[i - off];
        __syncthreads();
        if (i >= off) s[i] += t;
        __syncthreads();
    }
    u32 excl = s[i] - padded;
    g_offset[i] = excl;
    __syncthreads();
    // clear map, then each region fills its groups
    for (int g = i; g < NGRP; g += NREG) g_grpreg[g] = 0xFFFFu;
    __syncthreads();
    u32 gbase = excl >> 6, gcnt = padded >> 6;
    for (u32 g = 0; g < gcnt; ++g) g_grpreg[gbase + g] = (u16)i;
}

// ---------------- kernel 5: scatter pixel indices ----------------
__global__ void k_scatter() {
    int p = blockIdx.x * 256 + threadIdx.x;     // grid 2048
    int r = (int)g_pixreg[p];
    u32 slot = g_offset[r] + atomicAdd(&g_cursor[r], 1u);
    g_order[slot] = (u32)p;
}

// ---------------- kernel 6: binned shade, warp=region, 2 px/lane ----------------
__global__ void __launch_bounds__(256, 2) k_shade(const float* __restrict__ normal,
                                                  float* __restrict__ out) {
    __shared__ float4 tab[2 * 960];    // both batch tables, 30KB
    for (int i = threadIdx.x; i < 2 * 960; i += 256)
        tab[i] = ((const float4*)g_table)[i];
    __syncthreads();

    int grp = blockIdx.x * 8 + (threadIdx.x >> 5);   // < NGRP
    int lane = threadIdx.x & 31;
    u32 r = (u32)g_grpreg[grp];
    if (r == 0xFFFFu) return;                        // empty tail group
    int bucket = (int)(r & 255u);
    int batch  = (int)(r >> 8);
    u32 off = g_offset[r], cnt = g_hist[r];

    int s0 = grp * 64 + lane, s1 = s0 + 32;
    bool v0 = (u32)(s0 - off) < cnt;
    bool v1 = (u32)(s1 - off) < cnt;
    int p0 = v0 ? (int)g_order[s0] : 0;
    int p1 = v1 ? (int)g_order[s1] : 0;

    float gm = __uint_as_float(g_maxbits);
    float sc = 1.0f / gm;

    float ax, ay, az, bx, by, bz;
    load_normal(normal + p0 * 3, ax, ay, az);
    load_normal(normal + p1 * 3, bx, by, bz);
    u64 ax2 = dup2(ax * sc), ay2 = dup2(ay * sc), az2 = dup2(az * sc);
    u64 bx2 = dup2(bx * sc), by2 = dup2(by * sc), bz2 = dup2(bz * sc);

    int len = (int)g_listlen[bucket];
    const u16* L = g_list + bucket * 240;
    const float4* T = &tab[batch * 960];

    u64 ar0 = 0ull, ag0 = 0ull, ab0 = 0ull;
    u64 ar1 = 0ull, ag1 = 0ull, ab1 = 0ull;

    #pragma unroll 4
    for (int j = 0; j < len; ++j) {
        int mp = (int)__ldg(&L[j]);                  // warp-uniform
        float4 q0 = T[mp * 4 + 0];
        float4 q1 = T[mp * 4 + 1];
        float4 q2 = T[mp * 4 + 2];
        u64 hx01 = pk2(q0.x, q0.y), hy01 = pk2(q0.z, q0.w), hz01 = pk2(q1.x, q1.y);
        u64 wr01 = pk2(q1.z, q1.w), wg01 = pk2(q2.x, q2.y), wb01 = pk2(q2.z, q2.w);

        // pixel 0
        u64 sa = fma2_(ax2, hx01, fma2_(ay2, hy01, mul2_(az2, hz01)));
        u64 ua = relu2(sa);
        u64 ca = mul2_(ua, ua);
        ca = mul2_(ca, ca); ca = mul2_(ca, ca); ca = mul2_(ca, ca);
        ca = mul2_(ca, ca); ca = mul2_(ca, ca);
        ar0 = fma2_(ca, wr01, ar0);
        ag0 = fma2_(ca, wg01, ag0);
        ab0 = fma2_(ca, wb01, ab0);

        // pixel 1
        u64 sb = fma2_(bx2, hx01, fma2_(by2, hy01, mul2_(bz2, hz01)));
        u64 ub = relu2(sb);
        u64 cb = mul2_(ub, ub);
        cb = mul2_(cb, cb); cb = mul2_(cb, cb); cb = mul2_(cb, cb);
        cb = mul2_(cb, cb); cb = mul2_(cb, cb);
        ar1 = fma2_(cb, wr01, ar1);
        ag1 = fma2_(cb, wg01, ag1);
        ab1 = fma2_(cb, wb01, ab1);
    }

    float r0, r1, g0, g1, b0, b1;
    int ob = batch * 3 * HW;
    if (v0) {
        unpk2(ar0, r0, r1); unpk2(ag0, g0, g1); unpk2(ab0, b0, b1);
        int i = p0 & (HW - 1);
        out[ob + i]          = r0 + r1;
        out[ob + HW + i]     = g0 + g1;
        out[ob + 2 * HW + i] = b0 + b1;
    }
    if (v1) {
        unpk2(ar1, r0, r1); unpk2(ag1, g0, g1); unpk2(ab1, b0, b1);
        int i = p1 & (HW - 1);
        out[ob + i]          = r0 + r1;
        out[ob + HW + i]     = g0 + g1;
        out[ob + 2 * HW + i] = b0 + b1;
    }
}

// ---------------- launch ----------------
extern "C" void kernel_launch(void* const* d_in, const int* in_sizes, int n_in,
                              void* d_out, int out_size) {
    const float* env    = (const float*)d_in[0];
    const float* normal = (const float*)d_in[1];
    if (n_in >= 2 && in_sizes[0] > in_sizes[1]) {
        env    = (const float*)d_in[1];
        normal = (const float*)d_in[0];
    }
    k_setup<<<1, 512>>>(env);
    k_max<<<1024, 256>>>(normal);
    k_lists<<<1, 256>>>();
    k_hist<<<2048, 256>>>(normal);
    k_scan<<<1, NREG>>>();
    k_scatter<<<2048, 256>>>();
    k_shade<<<SGRID, 256>>>(normal, (float*)d_out);
}

// round 12
// speedup vs baseline: 1.6032x; 1.5451x over previous
#include <cuda_runtime.h>

typedef unsigned long long u64;
typedef unsigned int u32;
typedef unsigned short u16;

#define HW (512*512)            // 262144 pixels per batch
#define NPIX (2*HW)             // 524288
#define NBUCK 256               // 16x16 octahedral buckets
#define NREG (2*NBUCK)          // (batch,bucket) regions = 512
#define NSLOT (NPIX + NREG*64)  // 557056 slots (regions padded to 64)
#define NGRP (NSLOT/64)         // 8704 warp-groups
#define SGRID (NSLOT/512)       // 1088 shade blocks (8 warps x 64 slots)

// ---------------- device scratch ----------------
__device__ __align__(16) float g_table[2 * 240 * 16];
__device__ u32 g_maxbits;
__device__ u32 g_hist[NREG];
__device__ u32 g_offset[NREG];
__device__ u32 g_cursor[NREG];
__device__ u32 g_order[NSLOT];
__device__ u16 g_pixreg[NPIX];        // region per pixel (from k_max)
__device__ u16 g_grpreg[NGRP];        // region per 64-slot group (from k_scan)
__device__ u16 g_list[NBUCK * 240];   // per-bucket light-pair list
__device__ u32 g_listlen[NBUCK];

// ---------------- packed f32x2 helpers ----------------
__device__ __forceinline__ u64 pk2(float lo, float hi) {
    u64 r;
    asm("mov.b64 %0, {%1, %2};" : "=l"(r) : "r"(__float_as_uint(lo)), "r"(__float_as_uint(hi)));
    return r;
}
__device__ __forceinline__ void unpk2(u64 v, float& lo, float& hi) {
    u32 a, b;
    asm("mov.b64 {%0, %1}, %2;" : "=r"(a), "=r"(b) : "l"(v));
    lo = __uint_as_float(a); hi = __uint_as_float(b);
}
__device__ __forceinline__ u64 dup2(float x) { return pk2(x, x); }
__device__ __forceinline__ u64 fma2_(u64 a, u64 b, u64 c) {
    u64 d; asm("fma.rn.f32x2 %0, %1, %2, %3;" : "=l"(d) : "l"(a), "l"(b), "l"(c)); return d;
}
__device__ __forceinline__ u64 mul2_(u64 a, u64 b) {
    u64 d; asm("mul.rn.f32x2 %0, %1, %2;" : "=l"(d) : "l"(a), "l"(b)); return d;
}
__device__ __forceinline__ u64 relu2(u64 s) {
    u32 lo, hi;
    asm("mov.b64 {%0,%1}, %2;" : "=r"(lo), "=r"(hi) : "l"(s));
    asm("max.s32 %0, %0, 0;" : "+r"(lo));
    asm("max.s32 %0, %0, 0;" : "+r"(hi));
    u64 r;
    asm("mov.b64 %0, {%1,%2};" : "=l"(r) : "r"(lo), "r"(hi));
    return r;
}
__device__ __forceinline__ u64 max2_s32(u64 m, u64 s) {
    u32 ml, mh, sl, sh;
    asm("mov.b64 {%0,%1}, %2;" : "=r"(ml), "=r"(mh) : "l"(m));
    asm("mov.b64 {%0,%1}, %2;" : "=r"(sl), "=r"(sh) : "l"(s));
    asm("max.s32 %0, %0, %1;" : "+r"(ml) : "r"(sl));
    asm("max.s32 %0, %0, %1;" : "+r"(mh) : "r"(sh));
    u64 r;
    asm("mov.b64 %0, {%1,%2};" : "=l"(r) : "r"(ml), "r"(mh));
    return r;
}

// ---------------- octahedral bucket mapping ----------------
__device__ __forceinline__ int oct_bucket(float nx, float ny, float nz) {
    float a = fabsf(nx) + fabsf(ny) + fabsf(nz);
    float inva = 1.0f / fmaxf(a, 1e-20f);
    float u = nx * inva, v = ny * inva;
    if (nz < 0.0f) {
        float uu = copysignf(1.0f - fabsf(v), u);
        float vv = copysignf(1.0f - fabsf(u), v);
        u = uu; v = vv;
    }
    int bu = min(15, max(0, (int)((u * 0.5f + 0.5f) * 16.0f)));
    int bv = min(15, max(0, (int)((v * 0.5f + 0.5f) * 16.0f)));
    return bv * 16 + bu;
}
__device__ __forceinline__ void oct_decode(float u, float v, float& x, float& y, float& z) {
    float zz = 1.0f - fabsf(u) - fabsf(v);
    float uu = u, vv = v;
    if (zz < 0.0f) {
        uu = copysignf(1.0f - fabsf(v), u);
        vv = copysignf(1.0f - fabsf(u), v);
    }
    float inv = rsqrtf(uu * uu + vv * vv + zz * zz);
    x = uu * inv; y = vv * inv; z = zz * inv;
}

// ---------------- per-pixel normal prep ----------------
__device__ __forceinline__ void load_normal(const float* __restrict__ nptr,
                                            float& nx, float& ny, float& nz) {
    float c0 = nptr[0], c1 = nptr[1], c2 = nptr[2];
    nx = (c2 - 0.5f) * 2.0f;
    ny = (c1 - 0.5f) * 2.0f;
    nz = (c0 - 0.5f) * 2.0f;
    float nn = sqrtf(nx * nx + ny * ny + nz * nz);
    float iv = 1.0f / fmaxf(nn, 1e-12f);
    nx *= iv; ny *= iv; nz *= iv;
}

// ---------------- kernel 0: tables + counter reset ----------------
__global__ void k_setup(const float* __restrict__ env) {
    int m = threadIdx.x;              // 0..511
    if (m == 0) g_maxbits = 0u;
    g_hist[m] = 0u; g_cursor[m] = 0u;

    int eh = m >> 5, ew = m & 31;
    const float PI_F = 3.14159274101257324e+00f;
    float phi = ((float)eh * (1.0f / 16.0f)) * PI_F;
    float th  = (((float)ew * (1.0f / 32.0f)) * 2.0f) * PI_F;

    float sp = sinf(phi), cp = cosf(phi);
    float st = sinf(th),  ct = cosf(th);

    float hx = st * sp;
    float hy = cp;
    float hz = 1.0f - ct * sp;
    float nrm = sqrtf(hx * hx + hy * hy + hz * hz);
    float rin = 1.0f / nrm;
    hx *= rin; hy *= rin; hz *= rin;

    if (m >= 32) {                    // eh>=1: 480 lights -> 240 pairs
        int i = m - 32, mp = i >> 1, half = i & 1;
        const float SC = (float)(1.0 / 60.0);
        float sw = sp * SC;
        #pragma unroll
        for (int b = 0; b < 2; ++b) {
            float* row = g_table + (b * 240 + mp) * 16;
            row[0 + half]  = hx;
            row[2 + half]  = hy;
            row[4 + half]  = hz;
            const float* e = env + (b * 512 + m) * 3;
            row[6 + half]  = e[0] * sw;
            row[8 + half]  = e[1] * sw;
            row[10 + half] = e[2] * sw;
            if (half == 0) { row[12] = 0.f; row[13] = 0.f; row[14] = 0.f; row[15] = 0.f; }
        }
    }
}

// ---------------- kernel 1: global max + pixel-region histogram (fused) --------
__global__ void __launch_bounds__(256, 2) k_max(const float* __restrict__ normal) {
    __shared__ float4 tab[960];
    __shared__ float wm[8];
    __shared__ u32 sh[NREG];
    const float4* gt = (const float4*)g_table;
    for (int i = threadIdx.x; i < 960; i += 256) tab[i] = gt[i];
    for (int i = threadIdx.x; i < NREG; i += 256) sh[i] = 0u;
    __syncthreads();

    int p0 = blockIdx.x * 256 + threadIdx.x;
    int p1 = p0 + 262144;
    float ax, ay, az, bx, by, bz;
    load_normal(normal + p0 * 3, ax, ay, az);
    load_normal(normal + p1 * 3, bx, by, bz);

    // region classification (batch of p0 is 0 or 1 by p0>>18; p1 = p0+HW same pattern)
    int r0 = (p0 >> 18) * NBUCK + oct_bucket(ax, ay, az);
    int r1 = (p1 >> 18) * NBUCK + oct_bucket(bx, by, bz);
    g_pixreg[p0] = (u16)r0;
    g_pixreg[p1] = (u16)r1;
    atomicAdd(&sh[r0], 1u);
    atomicAdd(&sh[r1], 1u);

    u64 ax2 = dup2(ax), ay2 = dup2(ay), az2 = dup2(az);
    u64 bx2 = dup2(bx), by2 = dup2(by), bz2 = dup2(bz);

    const float R2I = 0.70710678118654752f;
    float mx = fmaxf(fmaxf((ay + az) * R2I, (by + bz) * R2I), 0.0f);

    u64 ma = 0ull, mb = 0ull;
    #pragma unroll 8
    for (int mp = 0; mp < 240; ++mp) {
        float4 q0 = tab[mp * 4 + 0];
        float4 q1 = tab[mp * 4 + 1];
        u64 hx01 = pk2(q0.x, q0.y), hy01 = pk2(q0.z, q0.w), hz01 = pk2(q1.x, q1.y);
        u64 sa = fma2_(ax2, hx01, fma2_(ay2, hy01, mul2_(az2, hz01)));
        u64 sb = fma2_(bx2, hx01, fma2_(by2, hy01, mul2_(bz2, hz01)));
        ma = max2_s32(ma, sa);
        mb = max2_s32(mb, sb);
    }
    float l0, h0, l1, h1;
    unpk2(ma, l0, h0); unpk2(mb, l1, h1);
    mx = fmaxf(mx, fmaxf(fmaxf(l0, h0), fmaxf(l1, h1)));

    #pragma unroll
    for (int o = 16; o; o >>= 1) mx = fmaxf(mx, __shfl_xor_sync(0xffffffffu, mx, o));
    if ((threadIdx.x & 31) == 0) wm[threadIdx.x >> 5] = mx;
    __syncthreads();
    if (threadIdx.x == 0) {
        float m2 = wm[0];
        #pragma unroll
        for (int i = 1; i < 8; ++i) m2 = fmaxf(m2, wm[i]);
        atomicMax(&g_maxbits, __float_as_uint(m2));
    }
    // flush histogram: warp lanes hit consecutive counters (proven-fast pattern)
    for (int i = threadIdx.x; i < NREG; i += 256)
        if (sh[i]) atomicAdd(&g_hist[i], sh[i]);
}

// ---------------- kernel 2: per-bucket light lists ----------------
__global__ void k_lists() {
    int k = threadIdx.x;              // bucket
    int bu = k & 15, bv = k >> 4;
    float uc = ((float)bu + 0.5f) * (1.0f / 16.0f) * 2.0f - 1.0f;
    float vc = ((float)bv + 0.5f) * (1.0f / 16.0f) * 2.0f - 1.0f;
    float cx, cy, cz;
    oct_decode(uc, vc, cx, cy, cz);

    float mind = 1.0f;
    #pragma unroll
    for (int c = 0; c < 4; ++c) {
        float ucr = ((float)(bu + (c & 1))) * (1.0f / 16.0f) * 2.0f - 1.0f;
        float vcr = ((float)(bv + (c >> 1))) * (1.0f / 16.0f) * 2.0f - 1.0f;
        float x, y, z;
        oct_decode(ucr, vcr, x, y, z);
        mind = fminf(mind, cx * x + cy * y + cz * z);
    }
    float gm = __uint_as_float(g_maxbits);
    float dth = fminf(0.70f * gm, 0.999f);
    float theta = acosf(dth) + acosf(fminf(fmaxf(mind, -1.0f), 1.0f)) + 0.09f;
    float cth = (theta >= 3.1f) ? -1.1f : cosf(theta);

    int cnt = 0;
    for (int mp = 0; mp < 240; ++mp) {
        const float* row = g_table + mp * 16;
        float d0 = cx * row[0] + cy * row[2] + cz * row[4];
        float d1 = cx * row[1] + cy * row[3] + cz * row[5];
        if (fmaxf(d0, d1) > cth) g_list[k * 240 + cnt++] = (u16)mp;
    }
    g_listlen[k] = (u32)cnt;
}

// ---------------- kernel 3: scan (pad 64) + group->region map ----------------
__global__ void k_scan() {
    __shared__ u32 s[NREG];
    int i = threadIdx.x;               // 512 threads
    u32 padded = (g_hist[i] + 63u) & ~63u;
    s[i] = padded;
    __syncthreads();
    for (int off = 1; off < NREG; off <<= 1) {
        u32 t = 0;
        if (i >= off) t = s[i - off];
        __syncthreads();
        if (i >= off) s[i] += t;
        __syncthreads();
    }
    u32 excl = s[i] - padded;
    g_offset[i] = excl;
    __syncthreads();
    for (int g = i; g < NGRP; g += NREG) g_grpreg[g] = 0xFFFFu;
    __syncthreads();
    u32 gbase = excl >> 6, gcnt = padded >> 6;
    for (u32 g = 0; g < gcnt; ++g) g_grpreg[gbase + g] = (u16)i;
}

// ---------------- kernel 4: scatter, block-aggregated atomics ----------------
__global__ void k_scatter() {
    __shared__ u32 cntLoc[NREG];
    __shared__ u32 baseLoc[NREG];
    for (int i = threadIdx.x; i < NREG; i += 256) cntLoc[i] = 0u;
    __syncthreads();

    int p = blockIdx.x * 256 + threadIdx.x;     // grid 2048
    int r = (int)g_pixreg[p];
    u32 rank = atomicAdd(&cntLoc[r], 1u);       // smem, spread addresses
    __syncthreads();
    // one global atomic per (block, nonzero region); lanes hit consecutive counters
    for (int i = threadIdx.x; i < NREG; i += 256)
        if (cntLoc[i]) baseLoc[i] = atomicAdd(&g_cursor[i], cntLoc[i]);
    __syncthreads();
    u32 slot = g_offset[r] + baseLoc[r] + rank;
    g_order[slot] = (u32)p;
}

// ---------------- kernel 5: binned shade, warp=region, 2 px/lane ----------------
__global__ void __launch_bounds__(256, 2) k_shade(const float* __restrict__ normal,
                                                  float* __restrict__ out) {
    __shared__ float4 tab[2 * 960];    // both batch tables, 30KB
    for (int i = threadIdx.x; i < 2 * 960; i += 256)
        tab[i] = ((const float4*)g_table)[i];
    __syncthreads();

    int grp = blockIdx.x * 8 + (threadIdx.x >> 5);   // < NGRP
    int lane = threadIdx.x & 31;
    u32 r = (u32)g_grpreg[grp];
    if (r == 0xFFFFu) return;                        // empty tail group
    int bucket = (int)(r & 255u);
    int batch  = (int)(r >> 8);
    u32 off = g_offset[r], cnt = g_hist[r];

    int s0 = grp * 64 + lane, s1 = s0 + 32;
    bool v0 = (u32)(s0 - off) < cnt;
    bool v1 = (u32)(s1 - off) < cnt;
    int p0 = v0 ? (int)g_order[s0] : 0;
    int p1 = v1 ? (int)g_order[s1] : 0;

    float gm = __uint_as_float(g_maxbits);
    float sc = 1.0f / gm;

    float ax, ay, az, bx, by, bz;
    load_normal(normal + p0 * 3, ax, ay, az);
    load_normal(normal + p1 * 3, bx, by, bz);
    u64 ax2 = dup2(ax * sc), ay2 = dup2(ay * sc), az2 = dup2(az * sc);
    u64 bx2 = dup2(bx * sc), by2 = dup2(by * sc), bz2 = dup2(bz * sc);

    int len = (int)g_listlen[bucket];
    const u16* L = g_list + bucket * 240;
    const float4* T = &tab[batch * 960];

    u64 ar0 = 0ull, ag0 = 0ull, ab0 = 0ull;
    u64 ar1 = 0ull, ag1 = 0ull, ab1 = 0ull;

    #pragma unroll 4
    for (int j = 0; j < len; ++j) {
        int mp = (int)__ldg(&L[j]);                  // warp-uniform
        float4 q0 = T[mp * 4 + 0];
        float4 q1 = T[mp * 4 + 1];
        float4 q2 = T[mp * 4 + 2];
        u64 hx01 = pk2(q0.x, q0.y), hy01 = pk2(q0.z, q0.w), hz01 = pk2(q1.x, q1.y);
        u64 wr01 = pk2(q1.z, q1.w), wg01 = pk2(q2.x, q2.y), wb01 = pk2(q2.z, q2.w);

        // pixel 0
        u64 sa = fma2_(ax2, hx01, fma2_(ay2, hy01, mul2_(az2, hz01)));
        u64 ua = relu2(sa);
        u64 ca = mul2_(ua, ua);
        ca = mul2_(ca, ca); ca = mul2_(ca, ca); ca = mul2_(ca, ca);
        ca = mul2_(ca, ca); ca = mul2_(ca, ca);
        ar0 = fma2_(ca, wr01, ar0);
        ag0 = fma2_(ca, wg01, ag0);
        ab0 = fma2_(ca, wb01, ab0);

        // pixel 1
        u64 sb = fma2_(bx2, hx01, fma2_(by2, hy01, mul2_(bz2, hz01)));
        u64 ub = relu2(sb);
        u64 cb = mul2_(ub, ub);
        cb = mul2_(cb, cb); cb = mul2_(cb, cb); cb = mul2_(cb, cb);
        cb = mul2_(cb, cb); cb = mul2_(cb, cb);
        ar1 = fma2_(cb, wr01, ar1);
        ag1 = fma2_(cb, wg01, ag1);
        ab1 = fma2_(cb, wb01, ab1);
    }

    float r0, r1, g0, g1, b0, b1;
    int ob = batch * 3 * HW;
    if (v0) {
        unpk2(ar0, r0, r1); unpk2(ag0, g0, g1); unpk2(ab0, b0, b1);
        int i = p0 & (HW - 1);
        out[ob + i]          = r0 + r1;
        out[ob + HW + i]     = g0 + g1;
        out[ob + 2 * HW + i] = b0 + b1;
    }
    if (v1) {
        unpk2(ar1, r0, r1); unpk2(ag1, g0, g1); unpk2(ab1, b0, b1);
        int i = p1 & (HW - 1);
        out[ob + i]          = r0 + r1;
        out[ob + HW + i]     = g0 + g1;
        out[ob + 2 * HW + i] = b0 + b1;
    }
}

// ---------------- launch ----------------
extern "C" void kernel_launch(void* const* d_in, const int* in_sizes, int n_in,
                              void* d_out, int out_size) {
    const float* env    = (const float*)d_in[0];
    const float* normal = (const float*)d_in[1];
    if (n_in >= 2 && in_sizes[0] > in_sizes[1]) {
        env    = (const float*)d_in[1];
        normal = (const float*)d_in[0];
    }
    k_setup<<<1, 512>>>(env);
    k_max<<<1024, 256>>>(normal);
    k_lists<<<1, 256>>>();
    k_scan<<<1, NREG>>>();
    k_scatter<<<2048, 256>>>();
    k_shade<<<SGRID, 256>>>(normal, (float*)d_out);
}

// round 13
// speedup vs baseline: 2.4015x; 1.4979x over previous
#include <cuda_runtime.h>

typedef unsigned long long u64;
typedef unsigned int u32;

#define HW (512*512)

// ---------------- device scratch ----------------
// Shade table: per batch b (2), per m-pair mp (240; eh>=1 lights only), 16 floats (64B):
//   [hx0,hx1, hy0,hy1, hz0,hz1, wr0,wr1, wg0,wg1, wb0,wb1, pad x4]
// w = env * sin(phi) / 60.  The 32 eh=0 lights have w == 0 exactly -> dropped from shade
// (but their direction h=(0,1,1)/sqrt2 still participates in the global max, analytically).
__device__ __align__(16) float g_table[2 * 240 * 16];
__device__ u32 g_maxbits;

// ---------------- packed f32x2 helpers ----------------
__device__ __forceinline__ u64 pk2(float lo, float hi) {
    u64 r;
    asm("mov.b64 %0, {%1, %2};" : "=l"(r) : "r"(__float_as_uint(lo)), "r"(__float_as_uint(hi)));
    return r;
}
__device__ __forceinline__ void unpk2(u64 v, float& lo, float& hi) {
    u32 a, b;
    asm("mov.b64 {%0, %1}, %2;" : "=r"(a), "=r"(b) : "l"(v));
    lo = __uint_as_float(a); hi = __uint_as_float(b);
}
__device__ __forceinline__ u64 dup2(float x) { return pk2(x, x); }
__device__ __forceinline__ u64 fma2_(u64 a, u64 b, u64 c) {
    u64 d; asm("fma.rn.f32x2 %0, %1, %2, %3;" : "=l"(d) : "l"(a), "l"(b), "l"(c)); return d;
}
__device__ __forceinline__ u64 mul2_(u64 a, u64 b) {
    u64 d; asm("mul.rn.f32x2 %0, %1, %2;" : "=l"(d) : "l"(a), "l"(b)); return d;
}
// packed relu: bits(relu(x)) == max_s32(bits(x), 0)
__device__ __forceinline__ u64 relu2(u64 s) {
    u32 lo, hi;
    asm("mov.b64 {%0,%1}, %2;" : "=r"(lo), "=r"(hi) : "l"(s));
    asm("max.s32 %0, %0, 0;" : "+r"(lo));
    asm("max.s32 %0, %0, 0;" : "+r"(hi));
    u64 r;
    asm("mov.b64 %0, {%1,%2};" : "=l"(r) : "r"(lo), "r"(hi));
    return r;
}
// packed running-max (halves of m >= 0, so s32 max == float max)
__device__ __forceinline__ u64 max2_s32(u64 m, u64 s) {
    u32 ml, mh, sl, sh;
    asm("mov.b64 {%0,%1}, %2;" : "=r"(ml), "=r"(mh) : "l"(m));
    asm("mov.b64 {%0,%1}, %2;" : "=r"(sl), "=r"(sh) : "l"(s));
    asm("max.s32 %0, %0, %1;" : "+r"(ml) : "r"(sl));
    asm("max.s32 %0, %0, %1;" : "+r"(mh) : "r"(sh));
    u64 r;
    asm("mov.b64 %0, {%1,%2};" : "=l"(r) : "r"(ml), "r"(mh));
    return r;
}

// ---------------- kernel 0: constants + table + scratch reset ----------------
__global__ void k_setup(const float* __restrict__ env) {
    int m = threadIdx.x;              // 0..511
    if (m == 0) g_maxbits = 0u;

    int eh = m >> 5, ew = m & 31;
    const float PI_F = 3.14159274101257324e+00f;
    float phi = ((float)eh * (1.0f / 16.0f)) * PI_F;
    float th  = (((float)ew * (1.0f / 32.0f)) * 2.0f) * PI_F;

    float sp = sinf(phi), cp = cosf(phi);
    float st = sinf(th),  ct = cosf(th);

    // l = (st*sp, cp, -ct*sp); v = (0,0,1); h = normalize(v + l)
    float hx = st * sp;
    float hy = cp;
    float hz = 1.0f - ct * sp;
    float nrm = sqrtf(hx * hx + hy * hy + hz * hz);
    float rin = 1.0f / nrm;
    hx *= rin; hy *= rin; hz *= rin;

    if (m >= 32) {                    // eh>=1: 480 lights -> 240 pairs
        int i = m - 32, mp = i >> 1, half = i & 1;
        const float SC = (float)(1.0 / 60.0);
        float sw = sp * SC;

        #pragma unroll
        for (int b = 0; b < 2; ++b) {
            float* row = g_table + (b * 240 + mp) * 16;
            row[0 + half]  = hx;
            row[2 + half]  = hy;
            row[4 + half]  = hz;
            const float* e = env + (b * 512 + m) * 3;
            row[6 + half]  = e[0] * sw;
            row[8 + half]  = e[1] * sw;
            row[10 + half] = e[2] * sw;
            if (half == 0) { row[12] = 0.f; row[13] = 0.f; row[14] = 0.f; row[15] = 0.f; }
        }
    }
}

// ---------------- per-pixel normal prep ----------------
__device__ __forceinline__ void load_normal(const float* __restrict__ nptr,
                                            float& nx, float& ny, float& nz) {
    float c0 = nptr[0], c1 = nptr[1], c2 = nptr[2];
    nx = (c2 - 0.5f) * 2.0f;
    ny = (c1 - 0.5f) * 2.0f;
    nz = (c0 - 0.5f) * 2.0f;
    float nn = sqrtf(nx * nx + ny * ny + nz * nz);
    float iv = 1.0f / fmaxf(nn, 1e-12f);
    nx *= iv; ny *= iv; nz *= iv;
}

// ---------------- kernel 1: fused UNSCALED shade + global-max tracking --------
// 2 pixels/thread, 240 pairs (R8-proven body). Accumulates sum(relu(s)^64 * w)
// without the 1/max normalization; tracks max(s) in spare ALU issue slots.
// The eh=0 lights (w==0) only matter for the max: dot = (ny+nz)/sqrt2, analytic.
__global__ void __launch_bounds__(256, 2) k_shade(const float* __restrict__ normal,
                                                  float* __restrict__ out) {
    __shared__ float4 tab[960];   // 15KB table for this batch
    __shared__ float wm[8];
    int b = blockIdx.y;
    const float4* gt = (const float4*)g_table + b * 960;
    for (int i = threadIdx.x; i < 960; i += 256) tab[i] = gt[i];
    __syncthreads();

    int i0 = blockIdx.x * 256 + threadIdx.x;     // 0..131071 within batch
    int i1 = i0 + 131072;

    float ax, ay, az, bx, by, bz;
    load_normal(normal + (b * HW + i0) * 3, ax, ay, az);
    load_normal(normal + (b * HW + i1) * 3, bx, by, bz);
    u64 ax2 = dup2(ax), ay2 = dup2(ay), az2 = dup2(az);
    u64 bx2 = dup2(bx), by2 = dup2(by), bz2 = dup2(bz);

    u64 ar0 = 0ull, ag0 = 0ull, ab0 = 0ull;
    u64 ar1 = 0ull, ag1 = 0ull, ab1 = 0ull;
    u64 ma = 0ull, mb = 0ull;                    // packed running max of s

    #pragma unroll 4
    for (int mp = 0; mp < 240; ++mp) {
        float4 q0 = tab[mp * 4 + 0];
        float4 q1 = tab[mp * 4 + 1];
        float4 q2 = tab[mp * 4 + 2];
        u64 hx01 = pk2(q0.x, q0.y), hy01 = pk2(q0.z, q0.w), hz01 = pk2(q1.x, q1.y);
        u64 wr01 = pk2(q1.z, q1.w), wg01 = pk2(q2.x, q2.y), wb01 = pk2(q2.z, q2.w);

        // pixel 0
        u64 sa = fma2_(ax2, hx01, fma2_(ay2, hy01, mul2_(az2, hz01)));
        ma = max2_s32(ma, sa);                   // ALU pipe, spare issue slots
        u64 ua = relu2(sa);
        u64 ca = mul2_(ua, ua);          // ^2
        ca = mul2_(ca, ca);              // ^4
        ca = mul2_(ca, ca);              // ^8
        ca = mul2_(ca, ca);              // ^16
        ca = mul2_(ca, ca);              // ^32
        ca = mul2_(ca, ca);              // ^64
        ar0 = fma2_(ca, wr01, ar0);
        ag0 = fma2_(ca, wg01, ag0);
        ab0 = fma2_(ca, wb01, ab0);

        // pixel 1
        u64 sb = fma2_(bx2, hx01, fma2_(by2, hy01, mul2_(bz2, hz01)));
        mb = max2_s32(mb, sb);
        u64 ub = relu2(sb);
        u64 cb = mul2_(ub, ub);
        cb = mul2_(cb, cb);
        cb = mul2_(cb, cb);
        cb = mul2_(cb, cb);
        cb = mul2_(cb, cb);
        cb = mul2_(cb, cb);
        ar1 = fma2_(cb, wr01, ar1);
        ag1 = fma2_(cb, wg01, ag1);
        ab1 = fma2_(cb, wb01, ab1);
    }

    // unscaled outputs
    float r0, r1, g0, g1, bb0, bb1;
    int ob = b * 3 * HW;
    unpk2(ar0, r0, r1); unpk2(ag0, g0, g1); unpk2(ab0, bb0, bb1);
    out[ob + i0]          = r0 + r1;
    out[ob + HW + i0]     = g0 + g1;
    out[ob + 2 * HW + i0] = bb0 + bb1;
    unpk2(ar1, r0, r1); unpk2(ag1, g0, g1); unpk2(ab1, bb0, bb1);
    out[ob + i1]          = r0 + r1;
    out[ob + HW + i1]     = g0 + g1;
    out[ob + 2 * HW + i1] = bb0 + bb1;

    // global-max reduction (include analytic eh=0 light)
    const float R2I = 0.70710678118654752f;      // 1/sqrt(2)
    float l0, h0, l1, h1;
    unpk2(ma, l0, h0); unpk2(mb, l1, h1);
    float mx = fmaxf(fmaxf(fmaxf(l0, h0), fmaxf(l1, h1)),
                     fmaxf(fmaxf((ay + az) * R2I, (by + bz) * R2I), 0.0f));
    #pragma unroll
    for (int o = 16; o; o >>= 1) mx = fmaxf(mx, __shfl_xor_sync(0xffffffffu, mx, o));
    if ((threadIdx.x & 31) == 0) wm[threadIdx.x >> 5] = mx;
    __syncthreads();
    if (threadIdx.x == 0) {
        float m2 = wm[0];
        #pragma unroll
        for (int i = 1; i < 8; ++i) m2 = fmaxf(m2, wm[i]);
        atomicMax(&g_maxbits, __float_as_uint(m2));  // nonneg bits monotone as uint
    }
}

// ---------------- kernel 2: scale epilogue: out *= 1/gm^64 ----------------
// gm^64 via the same 6-squaring sequence as the shade power, so the max element
// maps to exactly sum-consistent values (max term ratio == 1.0).
__global__ void k_scale(float* __restrict__ out) {
    float gm = __uint_as_float(g_maxbits);
    float g2 = gm * gm;            // ^2
    g2 = g2 * g2;                  // ^4
    g2 = g2 * g2;                  // ^8
    g2 = g2 * g2;                  // ^16
    g2 = g2 * g2;                  // ^32
    g2 = g2 * g2;                  // ^64
    float inv = 1.0f / g2;

    int i = blockIdx.x * 256 + threadIdx.x;      // grid 1536 -> 393216 float4
    float4* o4 = (float4*)out;
    float4 v = o4[i];
    v.x *= inv; v.y *= inv; v.z *= inv; v.w *= inv;
    o4[i] = v;
}

// ---------------- launch ----------------
extern "C" void kernel_launch(void* const* d_in, const int* in_sizes, int n_in,
                              void* d_out, int out_size) {
    const float* env    = (const float*)d_in[0];
    const float* normal = (const float*)d_in[1];
    if (n_in >= 2 && in_sizes[0] > in_sizes[1]) {
        env    = (const float*)d_in[1];
        normal = (const float*)d_in[0];
    }
    k_setup<<<1, 512>>>(env);
    k_shade<<<dim3(512, 2), 256>>>(normal, (float*)d_out);
    k_scale<<<1536, 256>>>((float*)d_out);
}

// round 14
// speedup vs baseline: 2.4471x; 1.0190x over previous
#include <cuda_runtime.h>

typedef unsigned long long u64;
typedef unsigned int u32;

#define HW (512*512)

// ---------------- device scratch ----------------
// Shade table: per batch b (2), per m-pair mp (240; eh>=1 lights only), 16 floats (64B):
//   [hx0,hx1, hy0,hy1, hz0,hz1, wr0,wr1, wg0,wg1, wb0,wb1, pad x4]
// w = env * sin(phi) / 60.  The 32 eh=0 lights have w == 0 exactly -> dropped from shade
// (their direction h=(0,1,1)/sqrt2 still participates in the global max, analytically).
__device__ __align__(16) float g_table[2 * 240 * 16];
__device__ u32 g_maxbits;

// ---------------- packed f32x2 helpers ----------------
__device__ __forceinline__ u64 pk2(float lo, float hi) {
    u64 r;
    asm("mov.b64 %0, {%1, %2};" : "=l"(r) : "r"(__float_as_uint(lo)), "r"(__float_as_uint(hi)));
    return r;
}
__device__ __forceinline__ void unpk2(u64 v, float& lo, float& hi) {
    u32 a, b;
    asm("mov.b64 {%0, %1}, %2;" : "=r"(a), "=r"(b) : "l"(v));
    lo = __uint_as_float(a); hi = __uint_as_float(b);
}
__device__ __forceinline__ u64 dup2(float x) { return pk2(x, x); }
__device__ __forceinline__ u64 fma2_(u64 a, u64 b, u64 c) {
    u64 d; asm("fma.rn.f32x2 %0, %1, %2, %3;" : "=l"(d) : "l"(a), "l"(b), "l"(c)); return d;
}
__device__ __forceinline__ u64 mul2_(u64 a, u64 b) {
    u64 d; asm("mul.rn.f32x2 %0, %1, %2;" : "=l"(d) : "l"(a), "l"(b)); return d;
}
// packed relu: bits(relu(x)) == max_s32(bits(x), 0)
__device__ __forceinline__ u64 relu2(u64 s) {
    u32 lo, hi;
    asm("mov.b64 {%0,%1}, %2;" : "=r"(lo), "=r"(hi) : "l"(s));
    asm("max.s32 %0, %0, 0;" : "+r"(lo));
    asm("max.s32 %0, %0, 0;" : "+r"(hi));
    u64 r;
    asm("mov.b64 %0, {%1,%2};" : "=l"(r) : "r"(lo), "r"(hi));
    return r;
}
// packed running-max (halves of m >= 0, so s32 max == float max)
__device__ __forceinline__ u64 max2_s32(u64 m, u64 s) {
    u32 ml, mh, sl, sh;
    asm("mov.b64 {%0,%1}, %2;" : "=r"(ml), "=r"(mh) : "l"(m));
    asm("mov.b64 {%0,%1}, %2;" : "=r"(sl), "=r"(sh) : "l"(s));
    asm("max.s32 %0, %0, %1;" : "+r"(ml) : "r"(sl));
    asm("max.s32 %0, %0, %1;" : "+r"(mh) : "r"(sh));
    u64 r;
    asm("mov.b64 %0, {%1,%2};" : "=l"(r) : "r"(ml), "r"(mh));
    return r;
}

// ---------------- kernel 0: constants + table + scratch reset ----------------
// 4 blocks x 256 threads: one (batch, light) per thread -> trig spread over 4 SMs.
__global__ void k_setup(const float* __restrict__ env) {
    int tid = blockIdx.x * 256 + threadIdx.x;    // 0..1023
    if (tid == 0) g_maxbits = 0u;
    int m = tid & 511;                           // light index
    int b = tid >> 9;                            // batch

    int eh = m >> 5, ew = m & 31;
    const float PI_F = 3.14159274101257324e+00f;
    float phi = ((float)eh * (1.0f / 16.0f)) * PI_F;
    float th  = (((float)ew * (1.0f / 32.0f)) * 2.0f) * PI_F;

    float sp = sinf(phi), cp = cosf(phi);
    float st = sinf(th),  ct = cosf(th);

    // l = (st*sp, cp, -ct*sp); v = (0,0,1); h = normalize(v + l)
    float hx = st * sp;
    float hy = cp;
    float hz = 1.0f - ct * sp;
    float nrm = sqrtf(hx * hx + hy * hy + hz * hz);
    float rin = 1.0f / nrm;
    hx *= rin; hy *= rin; hz *= rin;

    if (m >= 32) {                    // eh>=1: 480 lights -> 240 pairs
        int i = m - 32, mp = i >> 1, half = i & 1;
        const float SC = (float)(1.0 / 60.0);
        float sw = sp * SC;

        float* row = g_table + (b * 240 + mp) * 16;
        row[0 + half]  = hx;
        row[2 + half]  = hy;
        row[4 + half]  = hz;
        const float* e = env + (b * 512 + m) * 3;
        row[6 + half]  = e[0] * sw;
        row[8 + half]  = e[1] * sw;
        row[10 + half] = e[2] * sw;
        if (half == 0) { row[12] = 0.f; row[13] = 0.f; row[14] = 0.f; row[15] = 0.f; }
    }
}

// ---------------- per-pixel normal prep ----------------
__device__ __forceinline__ void load_normal(const float* __restrict__ nptr,
                                            float& nx, float& ny, float& nz) {
    float c0 = nptr[0], c1 = nptr[1], c2 = nptr[2];
    nx = (c2 - 0.5f) * 2.0f;
    ny = (c1 - 0.5f) * 2.0f;
    nz = (c0 - 0.5f) * 2.0f;
    float nn = sqrtf(nx * nx + ny * ny + nz * nz);
    float iv = 1.0f / fmaxf(nn, 1e-12f);
    nx *= iv; ny *= iv; nz *= iv;
}

// ---------------- kernel 1: fused UNSCALED shade + global-max tracking --------
// 2 pixels/thread, 240 pairs. Accumulates sum(relu(s)^64 * w) without the 1/max
// normalization; tracks max(s) in spare ALU issue slots.
__global__ void __launch_bounds__(256, 2) k_shade(const float* __restrict__ normal,
                                                  float* __restrict__ out) {
    __shared__ float4 tab[960];   // 15KB table for this batch
    __shared__ float wm[8];
    int b = blockIdx.y;
    const float4* gt = (const float4*)g_table + b * 960;
    for (int i = threadIdx.x; i < 960; i += 256) tab[i] = gt[i];
    __syncthreads();

    int i0 = blockIdx.x * 256 + threadIdx.x;     // 0..131071 within batch
    int i1 = i0 + 131072;

    float ax, ay, az, bx, by, bz;
    load_normal(normal + (b * HW + i0) * 3, ax, ay, az);
    load_normal(normal + (b * HW + i1) * 3, bx, by, bz);
    u64 ax2 = dup2(ax), ay2 = dup2(ay), az2 = dup2(az);
    u64 bx2 = dup2(bx), by2 = dup2(by), bz2 = dup2(bz);

    u64 ar0 = 0ull, ag0 = 0ull, ab0 = 0ull;
    u64 ar1 = 0ull, ag1 = 0ull, ab1 = 0ull;
    u64 ma = 0ull, mb = 0ull;                    // packed running max of s

    #pragma unroll 8
    for (int mp = 0; mp < 240; ++mp) {
        float4 q0 = tab[mp * 4 + 0];
        float4 q1 = tab[mp * 4 + 1];
        float4 q2 = tab[mp * 4 + 2];
        u64 hx01 = pk2(q0.x, q0.y), hy01 = pk2(q0.z, q0.w), hz01 = pk2(q1.x, q1.y);
        u64 wr01 = pk2(q1.z, q1.w), wg01 = pk2(q2.x, q2.y), wb01 = pk2(q2.z, q2.w);

        // pixel 0
        u64 sa = fma2_(ax2, hx01, fma2_(ay2, hy01, mul2_(az2, hz01)));
        ma = max2_s32(ma, sa);                   // ALU pipe, spare issue slots
        u64 ua = relu2(sa);
        u64 ca = mul2_(ua, ua);          // ^2
        ca = mul2_(ca, ca);              // ^4
        ca = mul2_(ca, ca);              // ^8
        ca = mul2_(ca, ca);              // ^16
        ca = mul2_(ca, ca);              // ^32
        ca = mul2_(ca, ca);              // ^64
        ar0 = fma2_(ca, wr01, ar0);
        ag0 = fma2_(ca, wg01, ag0);
        ab0 = fma2_(ca, wb01, ab0);

        // pixel 1
        u64 sb = fma2_(bx2, hx01, fma2_(by2, hy01, mul2_(bz2, hz01)));
        mb = max2_s32(mb, sb);
        u64 ub = relu2(sb);
        u64 cb = mul2_(ub, ub);
        cb = mul2_(cb, cb);
        cb = mul2_(cb, cb);
        cb = mul2_(cb, cb);
        cb = mul2_(cb, cb);
        cb = mul2_(cb, cb);
        ar1 = fma2_(cb, wr01, ar1);
        ag1 = fma2_(cb, wg01, ag1);
        ab1 = fma2_(cb, wb01, ab1);
    }

    // unscaled outputs
    float r0, r1, g0, g1, bb0, bb1;
    int ob = b * 3 * HW;
    unpk2(ar0, r0, r1); unpk2(ag0, g0, g1); unpk2(ab0, bb0, bb1);
    out[ob + i0]          = r0 + r1;
    out[ob + HW + i0]     = g0 + g1;
    out[ob + 2 * HW + i0] = bb0 + bb1;
    unpk2(ar1, r0, r1); unpk2(ag1, g0, g1); unpk2(ab1, bb0, bb1);
    out[ob + i1]          = r0 + r1;
    out[ob + HW + i1]     = g0 + g1;
    out[ob + 2 * HW + i1] = bb0 + bb1;

    // global-max reduction (include analytic eh=0 light h=(0,1,1)/sqrt2)
    const float R2I = 0.70710678118654752f;
    float l0, h0, l1, h1;
    unpk2(ma, l0, h0); unpk2(mb, l1, h1);
    float mx = fmaxf(fmaxf(fmaxf(l0, h0), fmaxf(l1, h1)),
                     fmaxf(fmaxf((ay + az) * R2I, (by + bz) * R2I), 0.0f));
    #pragma unroll
    for (int o = 16; o; o >>= 1) mx = fmaxf(mx, __shfl_xor_sync(0xffffffffu, mx, o));
    if ((threadIdx.x & 31) == 0) wm[threadIdx.x >> 5] = mx;
    __syncthreads();
    if (threadIdx.x == 0) {
        float m2 = wm[0];
        #pragma unroll
        for (int i = 1; i < 8; ++i) m2 = fmaxf(m2, wm[i]);
        atomicMax(&g_maxbits, __float_as_uint(m2));  // nonneg bits monotone as uint
    }
}

// ---------------- kernel 2: scale epilogue: out *= 1/gm^64 ----------------
__global__ void k_scale(float* __restrict__ out) {
    float gm = __uint_as_float(g_maxbits);
    float g2 = gm * gm;            // ^2
    g2 = g2 * g2;                  // ^4
    g2 = g2 * g2;                  // ^8
    g2 = g2 * g2;                  // ^16
    g2 = g2 * g2;                  // ^32
    g2 = g2 * g2;                  // ^64
    float inv = 1.0f / g2;

    int i = blockIdx.x * 256 + threadIdx.x;      // grid 1536 -> 393216 float4
    float4* o4 = (float4*)out;
    float4 v = o4[i];
    v.x *= inv; v.y *= inv; v.z *= inv; v.w *= inv;
    o4[i] = v;
}

// ---------------- launch ----------------
extern "C" void kernel_launch(void* const* d_in, const int* in_sizes, int n_in,
                              void* d_out, int out_size) {
    const float* env    = (const float*)d_in[0];
    const float* normal = (const float*)d_in[1];
    if (n_in >= 2 && in_sizes[0] > in_sizes[1]) {
        env    = (const float*)d_in[1];
        normal = (const float*)d_in[0];
    }
    k_setup<<<4, 256>>>(env);
    k_shade<<<dim3(512, 2), 256>>>(normal, (float*)d_out);
    k_scale<<<1536, 256>>>((float*)d_out);
}